// round 1
// baseline (speedup 1.0000x reference)
#include <cuda_runtime.h>
#include <cuda_bf16.h>

#define BATCH 8
#define SQN   512
#define SKN   512
#define DD    32
#define PACK  528          // 32*33/2
#define KF    1152         // padded feature dim (multiple of 8 and 4-float alignment)
#define FEAT_USED 1122     // 528+528+32+32+1+1

// scratch (allocation-free rule: __device__ globals)
static __device__ float g_F[(size_t)BATCH * SQN * KF];      // q-side features
static __device__ float g_G[(size_t)BATCH * SKN * KF];      // k-side features
static __device__ float g_score[(size_t)BATCH * SQN * SKN]; // js, then softmax in place

// ---------------------------------------------------------------------------
// Kernel 1: per-matrix Gauss-Jordan inverse + feature row construction.
// gridDim.x = 2*BATCH*SQN; first half = q matrices, second half = k matrices.
// ---------------------------------------------------------------------------
__global__ void __launch_bounds__(256) invert_features_kernel(
    const float* __restrict__ q_mean, const float* __restrict__ q_cov,
    const float* __restrict__ k_mean, const float* __restrict__ k_cov)
{
    __shared__ float M[32 * 65];   // augmented [A | I], stride 65
    __shared__ float Cv[32 * 33];  // copy of cov, stride 33
    __shared__ float mean_s[32];
    __shared__ float u_s[32];
    __shared__ float fac[32];
    __shared__ float s_val;

    const int tid = threadIdx.x;
    const int bid = blockIdx.x;
    const bool is_k = bid >= BATCH * SQN;
    const int idx = is_k ? bid - BATCH * SQN : bid;   // b*512 + s

    const float* cov  = (is_k ? k_cov  : q_cov ) + (size_t)idx * DD * DD;
    const float* mean = (is_k ? k_mean : q_mean) + (size_t)idx * DD;

    // load augmented matrix + cov copy
    for (int i = tid; i < 32 * 64; i += 256) {
        int r = i >> 6, c = i & 63;
        float v;
        if (c < 32) { v = cov[r * 32 + c]; Cv[r * 33 + c] = v; }
        else        { v = (c - 32 == r) ? 1.0f : 0.0f; }
        M[r * 65 + c] = v;
    }
    if (tid < 32) mean_s[tid] = mean[tid];
    __syncthreads();

    // Gauss-Jordan, no pivoting (SPD, diag-dominant)
    for (int p = 0; p < 32; ++p) {
        float pinv = 1.0f / M[p * 65 + p];
        if (tid < 32) fac[tid] = (tid == p) ? 0.0f : M[tid * 65 + p];
        __syncthreads();
        if (tid < 64) M[p * 65 + tid] *= pinv;
        __syncthreads();
        for (int i = tid; i < 32 * 64; i += 256) {
            int r = i >> 6, c = i & 63;
            if (r != p) M[r * 65 + c] -= fac[r] * M[p * 65 + c];
        }
        __syncthreads();
    }

    // u = Inv * mean ; s = mean . u
    if (tid < 32) {
        float acc = 0.0f;
        #pragma unroll
        for (int e = 0; e < 32; ++e) acc += M[tid * 65 + 32 + e] * mean_s[e];
        u_s[tid] = acc;
    }
    __syncthreads();
    if (tid == 0) {
        float a = 0.0f;
        #pragma unroll
        for (int e = 0; e < 32; ++e) a += mean_s[e] * u_s[e];
        s_val = a;
    }
    __syncthreads();

    float* row = (is_k ? g_G : g_F) + (size_t)idx * KF;

    // packed symmetric sections (upper triangle)
    for (int t = tid; t < PACK; t += 256) {
        // decode (d,e) from packed index
        int d = 0, rem = t, len = 32;
        while (rem >= len) { rem -= len; ++d; --len; }
        int e = d + rem;
        float cov_de = Cv[d * 33 + e];
        float inv_de = M[d * 65 + 32 + e];
        float mm = mean_s[d] * mean_s[e];
        float dbl = (d == e) ? 1.0f : 2.0f;
        if (!is_k) {
            row[t]        = (cov_de + mm) * dbl;  // Qhat, off-diag doubled
            row[PACK + t] = inv_de * dbl;         // Qinv, off-diag doubled
        } else {
            row[t]        = inv_de;               // Kinv
            row[PACK + t] = cov_de + mm;          // Khat
        }
    }
    if (tid < 32) {
        if (!is_k) { row[1056 + tid] = -2.0f * mean_s[tid]; row[1088 + tid] = -2.0f * u_s[tid]; }
        else       { row[1056 + tid] = u_s[tid];            row[1088 + tid] = mean_s[tid];      }
    }
    if (tid == 0) {
        if (!is_k) { row[1120] = s_val; row[1121] = 1.0f; }
        else       { row[1120] = 1.0f;  row[1121] = s_val; }
    }
    // zero padding [1122, 1152)
    if (tid >= 64 && tid < 64 + (KF - FEAT_USED)) row[FEAT_USED + (tid - 64)] = 0.0f;
}

// ---------------------------------------------------------------------------
// Kernel 2: js GEMM  C[q,k] = 0.25*(F[q,:].G[k,:] - 64)   (NT form)
// 128x128 tile, BK=8, 256 threads, 8x8 per thread, double-buffered smem
// ---------------------------------------------------------------------------
__global__ void __launch_bounds__(256) gemm_js_kernel()
{
    __shared__ float As[2][8][128];
    __shared__ float Bs[2][8][128];

    const int b  = blockIdx.z;
    const int m0 = blockIdx.y * 128;
    const int n0 = blockIdx.x * 128;
    const float* A  = g_F + (size_t)b * SQN * KF;
    const float* Bm = g_G + (size_t)b * SKN * KF;
    float* Cp = g_score + (size_t)b * SQN * SKN;

    const int tid  = threadIdx.x;
    const int lrow = tid >> 1;           // 0..127
    const int lk   = (tid & 1) * 4;      // 0 or 4
    const int ty   = tid >> 4;           // 0..15 (m)
    const int tx   = tid & 15;           // 0..15 (n)

    float acc[8][8];
    #pragma unroll
    for (int i = 0; i < 8; ++i)
        #pragma unroll
        for (int j = 0; j < 8; ++j) acc[i][j] = 0.0f;

    const int NT = KF / 8;   // 144
    float4 av = *(const float4*)(A  + (size_t)(m0 + lrow) * KF + lk);
    float4 bv = *(const float4*)(Bm + (size_t)(n0 + lrow) * KF + lk);
    As[0][lk + 0][lrow] = av.x; As[0][lk + 1][lrow] = av.y;
    As[0][lk + 2][lrow] = av.z; As[0][lk + 3][lrow] = av.w;
    Bs[0][lk + 0][lrow] = bv.x; Bs[0][lk + 1][lrow] = bv.y;
    Bs[0][lk + 2][lrow] = bv.z; Bs[0][lk + 3][lrow] = bv.w;
    __syncthreads();

    int buf = 0;
    for (int t = 0; t < NT; ++t) {
        if (t + 1 < NT) {
            av = *(const float4*)(A  + (size_t)(m0 + lrow) * KF + (t + 1) * 8 + lk);
            bv = *(const float4*)(Bm + (size_t)(n0 + lrow) * KF + (t + 1) * 8 + lk);
        }
        #pragma unroll
        for (int k = 0; k < 8; ++k) {
            float a[8], bb[8];
            *(float4*)(a)      = *(const float4*)&As[buf][k][ty * 8];
            *(float4*)(a + 4)  = *(const float4*)&As[buf][k][ty * 8 + 4];
            *(float4*)(bb)     = *(const float4*)&Bs[buf][k][tx * 8];
            *(float4*)(bb + 4) = *(const float4*)&Bs[buf][k][tx * 8 + 4];
            #pragma unroll
            for (int i = 0; i < 8; ++i)
                #pragma unroll
                for (int j = 0; j < 8; ++j) acc[i][j] += a[i] * bb[j];
        }
        if (t + 1 < NT) {
            As[buf ^ 1][lk + 0][lrow] = av.x; As[buf ^ 1][lk + 1][lrow] = av.y;
            As[buf ^ 1][lk + 2][lrow] = av.z; As[buf ^ 1][lk + 3][lrow] = av.w;
            Bs[buf ^ 1][lk + 0][lrow] = bv.x; Bs[buf ^ 1][lk + 1][lrow] = bv.y;
            Bs[buf ^ 1][lk + 2][lrow] = bv.z; Bs[buf ^ 1][lk + 3][lrow] = bv.w;
            __syncthreads();
            buf ^= 1;
        }
    }

    #pragma unroll
    for (int i = 0; i < 8; ++i) {
        int m = m0 + ty * 8 + i;
        #pragma unroll
        for (int j = 0; j < 8; ++j) {
            int n = n0 + tx * 8 + j;
            Cp[(size_t)m * SKN + n] = 0.25f * (acc[i][j] - 64.0f);
        }
    }
}

// ---------------------------------------------------------------------------
// Kernel 3: softmax over last dim (rows of 512), in place on g_score
// ---------------------------------------------------------------------------
__global__ void __launch_bounds__(256) softmax_kernel()
{
    __shared__ float red[256];
    float* row = g_score + (size_t)blockIdx.x * SKN;
    const int tid = threadIdx.x;

    float v0 = row[tid], v1 = row[tid + 256];
    float mx = fmaxf(v0, v1);
    red[tid] = mx;
    __syncthreads();
    for (int s = 128; s > 0; s >>= 1) {
        if (tid < s) red[tid] = fmaxf(red[tid], red[tid + s]);
        __syncthreads();
    }
    mx = red[0];
    __syncthreads();

    float e0 = __expf(v0 - mx), e1 = __expf(v1 - mx);
    red[tid] = e0 + e1;
    __syncthreads();
    for (int s = 128; s > 0; s >>= 1) {
        if (tid < s) red[tid] += red[tid + s];
        __syncthreads();
    }
    float inv = 1.0f / red[0];
    row[tid] = e0 * inv;
    row[tid + 256] = e1 * inv;
}

// ---------------------------------------------------------------------------
// Kernel 4: out_mean[b,q,d] = sum_k score * v_mean
// ---------------------------------------------------------------------------
__global__ void __launch_bounds__(256) outmean_kernel(
    const float* __restrict__ v_mean, float* __restrict__ out)
{
    int gid = blockIdx.x * 256 + threadIdx.x;      // 0 .. B*SQ*DD-1
    int d = gid & 31;
    int q = (gid >> 5) & 511;
    int b = gid >> 14;
    const float* srow = g_score + ((size_t)b * SQN + q) * SKN;
    const float* vm = v_mean + (size_t)b * SKN * DD;
    float acc = 0.0f;
    #pragma unroll 4
    for (int k = 0; k < SKN; ++k) acc += srow[k] * vm[k * DD + d];
    out[gid] = acc;
}

// ---------------------------------------------------------------------------
// Kernel 5: out_cov = score @ v_cov   (NN GEMM, per batch 512x512 * 512x1024)
// ---------------------------------------------------------------------------
__global__ void __launch_bounds__(256) gemm_outcov_kernel(
    const float* __restrict__ v_cov, float* __restrict__ out)
{
    __shared__ float As[2][8][128];
    __shared__ float Bs[2][8][128];

    const int b  = blockIdx.z;
    const int m0 = blockIdx.y * 128;
    const int n0 = blockIdx.x * 128;
    const int NCOL = DD * DD;   // 1024
    const float* A  = g_score + (size_t)b * SQN * SKN;
    const float* Bm = v_cov   + (size_t)b * SKN * NCOL;
    float* Cp = out + (size_t)b * SQN * NCOL;

    const int tid  = threadIdx.x;
    const int lrow = tid >> 1;
    const int lk   = (tid & 1) * 4;
    const int bkr  = tid >> 5;            // 0..7  (k for B tile)
    const int bnc  = (tid & 31) * 4;      // 0..124 (n for B tile)
    const int ty   = tid >> 4;
    const int tx   = tid & 15;

    float acc[8][8];
    #pragma unroll
    for (int i = 0; i < 8; ++i)
        #pragma unroll
        for (int j = 0; j < 8; ++j) acc[i][j] = 0.0f;

    const int NT = SKN / 8;   // 64
    float4 av = *(const float4*)(A  + (size_t)(m0 + lrow) * SKN + lk);
    float4 bv = *(const float4*)(Bm + (size_t)bkr * NCOL + n0 + bnc);
    As[0][lk + 0][lrow] = av.x; As[0][lk + 1][lrow] = av.y;
    As[0][lk + 2][lrow] = av.z; As[0][lk + 3][lrow] = av.w;
    *(float4*)&Bs[0][bkr][bnc] = bv;
    __syncthreads();

    int buf = 0;
    for (int t = 0; t < NT; ++t) {
        if (t + 1 < NT) {
            av = *(const float4*)(A  + (size_t)(m0 + lrow) * SKN + (t + 1) * 8 + lk);
            bv = *(const float4*)(Bm + (size_t)((t + 1) * 8 + bkr) * NCOL + n0 + bnc);
        }
        #pragma unroll
        for (int k = 0; k < 8; ++k) {
            float a[8], bb[8];
            *(float4*)(a)      = *(const float4*)&As[buf][k][ty * 8];
            *(float4*)(a + 4)  = *(const float4*)&As[buf][k][ty * 8 + 4];
            *(float4*)(bb)     = *(const float4*)&Bs[buf][k][tx * 8];
            *(float4*)(bb + 4) = *(const float4*)&Bs[buf][k][tx * 8 + 4];
            #pragma unroll
            for (int i = 0; i < 8; ++i)
                #pragma unroll
                for (int j = 0; j < 8; ++j) acc[i][j] += a[i] * bb[j];
        }
        if (t + 1 < NT) {
            As[buf ^ 1][lk + 0][lrow] = av.x; As[buf ^ 1][lk + 1][lrow] = av.y;
            As[buf ^ 1][lk + 2][lrow] = av.z; As[buf ^ 1][lk + 3][lrow] = av.w;
            *(float4*)&Bs[buf ^ 1][bkr][bnc] = bv;
            __syncthreads();
            buf ^= 1;
        }
    }

    #pragma unroll
    for (int i = 0; i < 8; ++i) {
        int m = m0 + ty * 8 + i;
        #pragma unroll
        for (int j = 0; j < 8; ++j) {
            int n = n0 + tx * 8 + j;
            Cp[(size_t)m * NCOL + n] = acc[i][j];
        }
    }
}

// ---------------------------------------------------------------------------
extern "C" void kernel_launch(void* const* d_in, const int* in_sizes, int n_in,
                              void* d_out, int out_size)
{
    const float* q_mean = (const float*)d_in[0];
    const float* q_cov  = (const float*)d_in[1];
    const float* k_mean = (const float*)d_in[2];
    const float* k_cov  = (const float*)d_in[3];
    const float* v_mean = (const float*)d_in[4];
    const float* v_cov  = (const float*)d_in[5];
    float* out = (float*)d_out;

    // 1. invert covariances + build feature rows
    invert_features_kernel<<<2 * BATCH * SQN, 256>>>(q_mean, q_cov, k_mean, k_cov);

    // 2. js scores via single feature GEMM
    gemm_js_kernel<<<dim3(SKN / 128, SQN / 128, BATCH), 256>>>();

    // 3. softmax over k
    softmax_kernel<<<BATCH * SQN, 256>>>();

    // 4. out_mean (first B*SQ*D floats of d_out)
    outmean_kernel<<<(BATCH * SQN * DD) / 256, 256>>>(v_mean, out);

    // 5. out_cov (remaining B*SQ*D*D floats)
    gemm_outcov_kernel<<<dim3((DD * DD) / 128, SQN / 128, BATCH), 256>>>(
        v_cov, out + (size_t)BATCH * SQN * DD);
}

// round 2
// speedup vs baseline: 1.0022x; 1.0022x over previous
#include <cuda_runtime.h>
#include <cuda_bf16.h>

#define BATCH 8
#define SQN   512
#define SKN   512
#define DD    32
#define PACK  528          // 32*33/2
#define KF    1152         // padded feature dim (multiple of 8 and 4-float alignment)
#define FEAT_USED 1122     // 528+528+32+32+1+1

// scratch (allocation-free rule: __device__ globals)
static __device__ float g_F[(size_t)BATCH * SQN * KF];      // q-side features
static __device__ float g_G[(size_t)BATCH * SKN * KF];      // k-side features
static __device__ float g_score[(size_t)BATCH * SQN * SKN]; // js, then softmax in place

// ---------------------------------------------------------------------------
// Kernel 1: per-matrix Gauss-Jordan inverse + feature row construction.
// gridDim.x = 2*BATCH*SQN; first half = q matrices, second half = k matrices.
// ---------------------------------------------------------------------------
__global__ void __launch_bounds__(256) invert_features_kernel(
    const float* __restrict__ q_mean, const float* __restrict__ q_cov,
    const float* __restrict__ k_mean, const float* __restrict__ k_cov)
{
    __shared__ float M[32 * 65];   // augmented [A | I], stride 65
    __shared__ float Cv[32 * 33];  // copy of cov, stride 33
    __shared__ float mean_s[32];
    __shared__ float u_s[32];
    __shared__ float fac[32];
    __shared__ float s_val;

    const int tid = threadIdx.x;
    const int bid = blockIdx.x;
    const bool is_k = bid >= BATCH * SQN;
    const int idx = is_k ? bid - BATCH * SQN : bid;   // b*512 + s

    const float* cov  = (is_k ? k_cov  : q_cov ) + (size_t)idx * DD * DD;
    const float* mean = (is_k ? k_mean : q_mean) + (size_t)idx * DD;

    // load augmented matrix + cov copy
    for (int i = tid; i < 32 * 64; i += 256) {
        int r = i >> 6, c = i & 63;
        float v;
        if (c < 32) { v = cov[r * 32 + c]; Cv[r * 33 + c] = v; }
        else        { v = (c - 32 == r) ? 1.0f : 0.0f; }
        M[r * 65 + c] = v;
    }
    if (tid < 32) mean_s[tid] = mean[tid];
    __syncthreads();

    // Gauss-Jordan, no pivoting (SPD, diag-dominant)
    for (int p = 0; p < 32; ++p) {
        float pinv = 1.0f / M[p * 65 + p];
        if (tid < 32) fac[tid] = (tid == p) ? 0.0f : M[tid * 65 + p];
        __syncthreads();
        if (tid < 64) M[p * 65 + tid] *= pinv;
        __syncthreads();
        for (int i = tid; i < 32 * 64; i += 256) {
            int r = i >> 6, c = i & 63;
            if (r != p) M[r * 65 + c] -= fac[r] * M[p * 65 + c];
        }
        __syncthreads();
    }

    // u = Inv * mean ; s = mean . u
    if (tid < 32) {
        float acc = 0.0f;
        #pragma unroll
        for (int e = 0; e < 32; ++e) acc += M[tid * 65 + 32 + e] * mean_s[e];
        u_s[tid] = acc;
    }
    __syncthreads();
    if (tid == 0) {
        float a = 0.0f;
        #pragma unroll
        for (int e = 0; e < 32; ++e) a += mean_s[e] * u_s[e];
        s_val = a;
    }
    __syncthreads();

    float* row = (is_k ? g_G : g_F) + (size_t)idx * KF;

    // packed symmetric sections (upper triangle)
    for (int t = tid; t < PACK; t += 256) {
        // decode (d,e) from packed index
        int d = 0, rem = t, len = 32;
        while (rem >= len) { rem -= len; ++d; --len; }
        int e = d + rem;
        float cov_de = Cv[d * 33 + e];
        float inv_de = M[d * 65 + 32 + e];
        float mm = mean_s[d] * mean_s[e];
        float dbl = (d == e) ? 1.0f : 2.0f;
        if (!is_k) {
            row[t]        = (cov_de + mm) * dbl;  // Qhat, off-diag doubled
            row[PACK + t] = inv_de * dbl;         // Qinv, off-diag doubled
        } else {
            row[t]        = inv_de;               // Kinv
            row[PACK + t] = cov_de + mm;          // Khat
        }
    }
    if (tid < 32) {
        if (!is_k) { row[1056 + tid] = -2.0f * mean_s[tid]; row[1088 + tid] = -2.0f * u_s[tid]; }
        else       { row[1056 + tid] = u_s[tid];            row[1088 + tid] = mean_s[tid];      }
    }
    if (tid == 0) {
        if (!is_k) { row[1120] = s_val; row[1121] = 1.0f; }
        else       { row[1120] = 1.0f;  row[1121] = s_val; }
    }
    // zero padding [1122, 1152)
    if (tid >= 64 && tid < 64 + (KF - FEAT_USED)) row[FEAT_USED + (tid - 64)] = 0.0f;
}

// ---------------------------------------------------------------------------
// Kernel 2: js GEMM  C[q,k] = 0.25*(F[q,:].G[k,:] - 64)   (NT form)
// 128x128 tile, BK=8, 256 threads, 8x8 per thread, double-buffered smem
// ---------------------------------------------------------------------------
__global__ void __launch_bounds__(256) gemm_js_kernel()
{
    __shared__ float As[2][8][128];
    __shared__ float Bs[2][8][128];

    const int b  = blockIdx.z;
    const int m0 = blockIdx.y * 128;
    const int n0 = blockIdx.x * 128;
    const float* A  = g_F + (size_t)b * SQN * KF;
    const float* Bm = g_G + (size_t)b * SKN * KF;
    float* Cp = g_score + (size_t)b * SQN * SKN;

    const int tid  = threadIdx.x;
    const int lrow = tid >> 1;           // 0..127
    const int lk   = (tid & 1) * 4;      // 0 or 4
    const int ty   = tid >> 4;           // 0..15 (m)
    const int tx   = tid & 15;           // 0..15 (n)

    float acc[8][8];
    #pragma unroll
    for (int i = 0; i < 8; ++i)
        #pragma unroll
        for (int j = 0; j < 8; ++j) acc[i][j] = 0.0f;

    const int NT = KF / 8;   // 144
    float4 av = *(const float4*)(A  + (size_t)(m0 + lrow) * KF + lk);
    float4 bv = *(const float4*)(Bm + (size_t)(n0 + lrow) * KF + lk);
    As[0][lk + 0][lrow] = av.x; As[0][lk + 1][lrow] = av.y;
    As[0][lk + 2][lrow] = av.z; As[0][lk + 3][lrow] = av.w;
    Bs[0][lk + 0][lrow] = bv.x; Bs[0][lk + 1][lrow] = bv.y;
    Bs[0][lk + 2][lrow] = bv.z; Bs[0][lk + 3][lrow] = bv.w;
    __syncthreads();

    int buf = 0;
    for (int t = 0; t < NT; ++t) {
        if (t + 1 < NT) {
            av = *(const float4*)(A  + (size_t)(m0 + lrow) * KF + (t + 1) * 8 + lk);
            bv = *(const float4*)(Bm + (size_t)(n0 + lrow) * KF + (t + 1) * 8 + lk);
        }
        #pragma unroll
        for (int k = 0; k < 8; ++k) {
            float a[8], bb[8];
            *(float4*)(a)      = *(const float4*)&As[buf][k][ty * 8];
            *(float4*)(a + 4)  = *(const float4*)&As[buf][k][ty * 8 + 4];
            *(float4*)(bb)     = *(const float4*)&Bs[buf][k][tx * 8];
            *(float4*)(bb + 4) = *(const float4*)&Bs[buf][k][tx * 8 + 4];
            #pragma unroll
            for (int i = 0; i < 8; ++i)
                #pragma unroll
                for (int j = 0; j < 8; ++j) acc[i][j] += a[i] * bb[j];
        }
        if (t + 1 < NT) {
            As[buf ^ 1][lk + 0][lrow] = av.x; As[buf ^ 1][lk + 1][lrow] = av.y;
            As[buf ^ 1][lk + 2][lrow] = av.z; As[buf ^ 1][lk + 3][lrow] = av.w;
            Bs[buf ^ 1][lk + 0][lrow] = bv.x; Bs[buf ^ 1][lk + 1][lrow] = bv.y;
            Bs[buf ^ 1][lk + 2][lrow] = bv.z; Bs[buf ^ 1][lk + 3][lrow] = bv.w;
            __syncthreads();
            buf ^= 1;
        }
    }

    #pragma unroll
    for (int i = 0; i < 8; ++i) {
        int m = m0 + ty * 8 + i;
        #pragma unroll
        for (int j = 0; j < 8; ++j) {
            int n = n0 + tx * 8 + j;
            Cp[(size_t)m * SKN + n] = 0.25f * (acc[i][j] - 64.0f);
        }
    }
}

// ---------------------------------------------------------------------------
// Kernel 3: softmax over last dim (rows of 512), in place on g_score
// ---------------------------------------------------------------------------
__global__ void __launch_bounds__(256) softmax_kernel()
{
    __shared__ float red[256];
    float* row = g_score + (size_t)blockIdx.x * SKN;
    const int tid = threadIdx.x;

    float v0 = row[tid], v1 = row[tid + 256];
    float mx = fmaxf(v0, v1);
    red[tid] = mx;
    __syncthreads();
    for (int s = 128; s > 0; s >>= 1) {
        if (tid < s) red[tid] = fmaxf(red[tid], red[tid + s]);
        __syncthreads();
    }
    mx = red[0];
    __syncthreads();

    float e0 = __expf(v0 - mx), e1 = __expf(v1 - mx);
    red[tid] = e0 + e1;
    __syncthreads();
    for (int s = 128; s > 0; s >>= 1) {
        if (tid < s) red[tid] += red[tid + s];
        __syncthreads();
    }
    float inv = 1.0f / red[0];
    row[tid] = e0 * inv;
    row[tid + 256] = e1 * inv;
}

// ---------------------------------------------------------------------------
// Kernel 4: out_mean[b,q,d] = sum_k score * v_mean
// ---------------------------------------------------------------------------
__global__ void __launch_bounds__(256) outmean_kernel(
    const float* __restrict__ v_mean, float* __restrict__ out)
{
    int gid = blockIdx.x * 256 + threadIdx.x;      // 0 .. B*SQ*DD-1
    int d = gid & 31;
    int q = (gid >> 5) & 511;
    int b = gid >> 14;
    const float* srow = g_score + ((size_t)b * SQN + q) * SKN;
    const float* vm = v_mean + (size_t)b * SKN * DD;
    float acc = 0.0f;
    #pragma unroll 4
    for (int k = 0; k < SKN; ++k) acc += srow[k] * vm[k * DD + d];
    out[gid] = acc;
}

// ---------------------------------------------------------------------------
// Kernel 5: out_cov = score @ v_cov   (NN GEMM, per batch 512x512 * 512x1024)
// ---------------------------------------------------------------------------
__global__ void __launch_bounds__(256) gemm_outcov_kernel(
    const float* __restrict__ v_cov, float* __restrict__ out)
{
    __shared__ float As[2][8][128];
    __shared__ float Bs[2][8][128];

    const int b  = blockIdx.z;
    const int m0 = blockIdx.y * 128;
    const int n0 = blockIdx.x * 128;
    const int NCOL = DD * DD;   // 1024
    const float* A  = g_score + (size_t)b * SQN * SKN;
    const float* Bm = v_cov   + (size_t)b * SKN * NCOL;
    float* Cp = out + (size_t)b * SQN * NCOL;

    const int tid  = threadIdx.x;
    const int lrow = tid >> 1;
    const int lk   = (tid & 1) * 4;
    const int bkr  = tid >> 5;            // 0..7  (k for B tile)
    const int bnc  = (tid & 31) * 4;      // 0..124 (n for B tile)
    const int ty   = tid >> 4;
    const int tx   = tid & 15;

    float acc[8][8];
    #pragma unroll
    for (int i = 0; i < 8; ++i)
        #pragma unroll
        for (int j = 0; j < 8; ++j) acc[i][j] = 0.0f;

    const int NT = SKN / 8;   // 64
    float4 av = *(const float4*)(A  + (size_t)(m0 + lrow) * SKN + lk);
    float4 bv = *(const float4*)(Bm + (size_t)bkr * NCOL + n0 + bnc);
    As[0][lk + 0][lrow] = av.x; As[0][lk + 1][lrow] = av.y;
    As[0][lk + 2][lrow] = av.z; As[0][lk + 3][lrow] = av.w;
    *(float4*)&Bs[0][bkr][bnc] = bv;
    __syncthreads();

    int buf = 0;
    for (int t = 0; t < NT; ++t) {
        if (t + 1 < NT) {
            av = *(const float4*)(A  + (size_t)(m0 + lrow) * SKN + (t + 1) * 8 + lk);
            bv = *(const float4*)(Bm + (size_t)((t + 1) * 8 + bkr) * NCOL + n0 + bnc);
        }
        #pragma unroll
        for (int k = 0; k < 8; ++k) {
            float a[8], bb[8];
            *(float4*)(a)      = *(const float4*)&As[buf][k][ty * 8];
            *(float4*)(a + 4)  = *(const float4*)&As[buf][k][ty * 8 + 4];
            *(float4*)(bb)     = *(const float4*)&Bs[buf][k][tx * 8];
            *(float4*)(bb + 4) = *(const float4*)&Bs[buf][k][tx * 8 + 4];
            #pragma unroll
            for (int i = 0; i < 8; ++i)
                #pragma unroll
                for (int j = 0; j < 8; ++j) acc[i][j] += a[i] * bb[j];
        }
        if (t + 1 < NT) {
            As[buf ^ 1][lk + 0][lrow] = av.x; As[buf ^ 1][lk + 1][lrow] = av.y;
            As[buf ^ 1][lk + 2][lrow] = av.z; As[buf ^ 1][lk + 3][lrow] = av.w;
            *(float4*)&Bs[buf ^ 1][bkr][bnc] = bv;
            __syncthreads();
            buf ^= 1;
        }
    }

    #pragma unroll
    for (int i = 0; i < 8; ++i) {
        int m = m0 + ty * 8 + i;
        #pragma unroll
        for (int j = 0; j < 8; ++j) {
            int n = n0 + tx * 8 + j;
            Cp[(size_t)m * NCOL + n] = acc[i][j];
        }
    }
}

// ---------------------------------------------------------------------------
extern "C" void kernel_launch(void* const* d_in, const int* in_sizes, int n_in,
                              void* d_out, int out_size)
{
    const float* q_mean = (const float*)d_in[0];
    const float* q_cov  = (const float*)d_in[1];
    const float* k_mean = (const float*)d_in[2];
    const float* k_cov  = (const float*)d_in[3];
    const float* v_mean = (const float*)d_in[4];
    const float* v_cov  = (const float*)d_in[5];
    float* out = (float*)d_out;

    // 1. invert covariances + build feature rows
    invert_features_kernel<<<2 * BATCH * SQN, 256>>>(q_mean, q_cov, k_mean, k_cov);

    // 2. js scores via single feature GEMM
    gemm_js_kernel<<<dim3(SKN / 128, SQN / 128, BATCH), 256>>>();

    // 3. softmax over k
    softmax_kernel<<<BATCH * SQN, 256>>>();

    // 4. out_mean (first B*SQ*D floats of d_out)
    outmean_kernel<<<(BATCH * SQN * DD) / 256, 256>>>(v_mean, out);

    // 5. out_cov (remaining B*SQ*D*D floats)
    gemm_outcov_kernel<<<dim3((DD * DD) / 128, SQN / 128, BATCH), 256>>>(
        v_cov, out + (size_t)BATCH * SQN * DD);
}

// round 6
// speedup vs baseline: 1.3030x; 1.3001x over previous
#include <cuda_runtime.h>
#include <cuda_bf16.h>
#include <cstdint>

#define BATCH 8
#define SQN 512
#define DDIM 32
#define PACK 528
typedef unsigned short u16;
typedef unsigned int u32;

// scratch (__device__ globals, referenced ONLY inside device code)
static __device__ __align__(16) u16 g_F[(size_t)BATCH*SQN*2304];   // q feats [hi|lo]
static __device__ __align__(16) u16 g_G[(size_t)BATCH*SQN*2304];   // k feats [hi|lo]
static __device__ __align__(16) u16 g_S[(size_t)BATCH*SQN*1024];   // score  [hi|lo]
static __device__ __align__(16) u16 g_V[(size_t)BATCH*1024*1024];  // vcov^T [hi|lo]
static __device__ __align__(16) float g_js[(size_t)BATCH*SQN*SQN];

__device__ __forceinline__ u16 f2bf(float x){ __nv_bfloat16 h=__float2bfloat16(x); return *(u16*)&h; }
__device__ __forceinline__ float bf2f(u16 u){ __nv_bfloat16 h=*(__nv_bfloat16*)&u; return __bfloat162float(h); }
__device__ __forceinline__ u32 hilo(float x0,float x1,int lo){
    u16 h0=f2bf(x0), h1=f2bf(x1);
    if(lo){ h0=f2bf(x0-bf2f(h0)); h1=f2bf(x1-bf2f(h1)); }
    return (u32)h0 | ((u32)h1<<16);
}

// ---------------------------------------------------------------- featurize
__global__ void __launch_bounds__(256) feat_kernel(
    const float* __restrict__ q_mean,const float* __restrict__ q_cov,
    const float* __restrict__ k_mean,const float* __restrict__ k_cov)
{
    __shared__ float M[32*65]; __shared__ float Cv[32*33];
    __shared__ float mean_s[32],u_s[32],fac[32]; __shared__ float s_val;
    __shared__ float f[1152];
    const int tid=threadIdx.x, bid=blockIdx.x;
    const bool is_k = bid >= BATCH*SQN;
    const int idx = is_k ? bid-BATCH*SQN : bid;
    const float* cov =(is_k?k_cov :q_cov )+(size_t)idx*DDIM*DDIM;
    const float* mean=(is_k?k_mean:q_mean)+(size_t)idx*DDIM;

    for(int i=tid;i<32*64;i+=256){ int r=i>>6,c=i&63; float v;
        if(c<32){ v=cov[r*32+c]; Cv[r*33+c]=v; } else v=(c-32==r)?1.f:0.f;
        M[r*65+c]=v; }
    if(tid<32) mean_s[tid]=mean[tid];
    __syncthreads();
    for(int p=0;p<32;p++){
        float pinv=1.f/M[p*65+p];
        if(tid<32) fac[tid]=(tid==p)?0.f:M[tid*65+p];
        __syncthreads();
        if(tid<64) M[p*65+tid]*=pinv;
        __syncthreads();
        for(int i=tid;i<32*64;i+=256){ int r=i>>6,c=i&63;
            if(r!=p) M[r*65+c]-=fac[r]*M[p*65+c]; }
        __syncthreads();
    }
    if(tid<32){ float a=0.f;
        #pragma unroll
        for(int e=0;e<32;e++) a+=M[tid*65+32+e]*mean_s[e];
        u_s[tid]=a; }
    __syncthreads();
    if(tid==0){ float a=0.f;
        #pragma unroll
        for(int e=0;e<32;e++) a+=mean_s[e]*u_s[e];
        s_val=a; }
    __syncthreads();
    for(int t=tid;t<PACK;t+=256){
        int d=0,rem=t,len=32; while(rem>=len){rem-=len;++d;--len;} int e=d+rem;
        float cov_de=Cv[d*33+e], inv_de=M[d*65+32+e];
        float mm=mean_s[d]*mean_s[e], dbl=(d==e)?1.f:2.f;
        if(!is_k){ f[t]=(cov_de+mm)*dbl; f[PACK+t]=inv_de*dbl; }
        else     { f[t]=inv_de;          f[PACK+t]=cov_de+mm; }
    }
    if(tid<32){
        if(!is_k){ f[1056+tid]=-2.f*mean_s[tid]; f[1088+tid]=-2.f*u_s[tid]; }
        else     { f[1056+tid]=u_s[tid];         f[1088+tid]=mean_s[tid];   }
    }
    if(tid==0){ if(!is_k){ f[1120]=s_val; f[1121]=1.f; } else { f[1120]=1.f; f[1121]=s_val; } }
    if(tid<30) f[1122+tid]=0.f;
    __syncthreads();
    u32* rowp=(u32*)((is_k?g_G:g_F)+(size_t)idx*2304);
    for(int j=tid;j<576;j+=256){
        float x0=f[2*j],x1=f[2*j+1];
        rowp[j]    =hilo(x0,x1,0);
        rowp[576+j]=hilo(x0,x1,1);
    }
}

// ---------------------------------------------------------------- vcov transpose+split
__global__ void __launch_bounds__(256) vsplit_kernel(const float* __restrict__ vcov)
{
    __shared__ float ts[64*129];
    const int n0=blockIdx.x*128, k0=blockIdx.y*64, b=blockIdx.z, tid=threadIdx.x;
    const float* src=vcov+((size_t)b*512+k0)*1024+n0;
    for(int i=tid;i<8192;i+=256){ int kk=i>>7,nn=i&127; ts[kk*129+nn]=src[(size_t)kk*1024+nn]; }
    __syncthreads();
    u32* dst=(u32*)g_V;
    for(int i=tid;i<4096;i+=256){
        int nl=i>>5, kp=i&31;
        float x0=ts[(kp*2)*129+nl], x1=ts[(kp*2+1)*129+nl];
        size_t rb=((size_t)b*1024+n0+nl)*512;
        dst[rb+(blockIdx.y*32)+kp]     =hilo(x0,x1,0);
        dst[rb+256+(blockIdx.y*32)+kp] =hilo(x0,x1,1);
    }
}

// ---------------------------------------------------------------- softmax + out_mean + S split
__global__ void __launch_bounds__(256) softmax_kernel(const float* __restrict__ vmean,
                                                      float* __restrict__ out_mean)
{
    __shared__ float p[512]; __shared__ float red[256];
    const int gid=blockIdx.x, tid=threadIdx.x, b=gid>>9;
    const float* row=g_js+(size_t)gid*512;
    float v0=row[tid], v1=row[tid+256];
    red[tid]=fmaxf(v0,v1); __syncthreads();
    for(int s=128;s>0;s>>=1){ if(tid<s) red[tid]=fmaxf(red[tid],red[tid+s]); __syncthreads(); }
    float mx=red[0]; __syncthreads();
    float e0=__expf(v0-mx), e1=__expf(v1-mx);
    red[tid]=e0+e1; __syncthreads();
    for(int s=128;s>0;s>>=1){ if(tid<s) red[tid]+=red[tid+s]; __syncthreads(); }
    float inv=1.f/red[0]; __syncthreads();
    float p0=e0*inv, p1=e1*inv;
    p[tid]=p0; p[tid+256]=p1;
    __syncthreads();
    u32* srow=(u32*)(g_S+(size_t)gid*1024);
    {
        float x0=p[2*tid], x1=p[2*tid+1];
        srow[tid]=hilo(x0,x1,0); srow[256+tid]=hilo(x0,x1,1);
    }
    const float* vm=vmean+(size_t)b*512*32;
    int d=tid&31, kg=tid>>5;
    float acc=0.f;
    #pragma unroll 4
    for(int i=0;i<64;i++){ int k=kg*64+i; acc+=p[k]*vm[k*32+d]; }
    red[tid]=acc; __syncthreads();
    if(tid<128) red[tid]+=red[tid+128]; __syncthreads();
    if(tid<64)  red[tid]+=red[tid+64];  __syncthreads();
    if(tid<32)  out_mean[(size_t)gid*32+tid]=red[tid]+red[tid+32];
}

// ---------------------------------------------------------------- bf16 mma.sync GEMM
// MODE 0: js (A=g_F,B=g_G,C=g_js).  MODE 1: out_cov (A=g_S,B=g_V,C=arg).
// NT, 128x128 CTA tile, 8 warps (64x32 each), K-chunks of 32.
template<int NK,int KCH,int HL,int LDA,int LDB,int NBROWS,int LDC,int MODE>
__global__ void __launch_bounds__(256,2) gemm_mma(float* __restrict__ Carg)
{
    __shared__ __align__(16) u16 sA[128*40];   // 40 u16 = 80B row stride
    __shared__ __align__(16) u16 sB[128*40];
    const int tid=threadIdx.x, wid=tid>>5, lid=tid&31;
    const int wm=wid&1, wn=wid>>1;             // warp tile: rows wm*64, cols wn*32
    const int nb=blockIdx.x, mb=blockIdx.y, b=blockIdx.z;

    const u16* Ag = (MODE==0) ? g_F : g_S;     // device-side symbol resolution
    const u16* Bg = (MODE==0) ? g_G : g_V;
    float*     Cg = (MODE==0) ? g_js : Carg;

    const u16* Ab=Ag+(size_t)(b*512   +mb*128)*LDA;
    const u16* Bb=Bg+(size_t)(b*NBROWS+nb*128)*LDB;

    const int ar0=tid>>2, ac0=tid&3;
    const int ar1=(tid+256)>>2;
    uint4 ra0,ra1,rb0,rb1;

    auto gload=[&](int t){
        int blk=t/KCH, tt=t-blk*KCH;
        int aoff=((blk==2)?HL:0)+tt*32;
        int boff=((blk==1)?HL:0)+tt*32;
        ra0=*(const uint4*)(Ab+(size_t)ar0*LDA+aoff+ac0*8);
        ra1=*(const uint4*)(Ab+(size_t)ar1*LDA+aoff+ac0*8);
        rb0=*(const uint4*)(Bb+(size_t)ar0*LDB+boff+ac0*8);
        rb1=*(const uint4*)(Bb+(size_t)ar1*LDB+boff+ac0*8);
    };

    const int fr=lid>>2, fc=lid&3;   // PTX mma fragment lane decomposition
    float acc[4][4][4];
    #pragma unroll
    for(int f=0;f<4;f++)
        #pragma unroll
        for(int n=0;n<4;n++)
            #pragma unroll
            for(int e=0;e<4;e++) acc[f][n][e]=0.f;

    gload(0);
    #pragma unroll 1
    for(int t=0;t<NK;t++){
        *(uint4*)(sA+ar0*40+ac0*8)=ra0;
        *(uint4*)(sA+ar1*40+ac0*8)=ra1;
        *(uint4*)(sB+ar0*40+ac0*8)=rb0;
        *(uint4*)(sB+ar1*40+ac0*8)=rb1;
        __syncthreads();
        if(t+1<NK) gload(t+1);
        #pragma unroll
        for(int ks=0;ks<2;ks++){
            u32 a[4][4], bb[4][2];
            #pragma unroll
            for(int f=0;f<4;f++){
                const u16* base=sA+(wm*64+f*16+fr)*40+ks*16+fc*2;
                a[f][0]=*(const u32*)(base);        // row fr,   k 2fc,2fc+1
                a[f][1]=*(const u32*)(base+8*40);   // row fr+8
                a[f][2]=*(const u32*)(base+8);      // k +8
                a[f][3]=*(const u32*)(base+8*40+8);
            }
            #pragma unroll
            for(int n=0;n<4;n++){
                const u16* base=sB+(wn*32+n*8+fr)*40+ks*16+fc*2;
                bb[n][0]=*(const u32*)(base);       // n fr, k 2fc
                bb[n][1]=*(const u32*)(base+8);     // k +8
            }
            #pragma unroll
            for(int f=0;f<4;f++)
                #pragma unroll
                for(int n=0;n<4;n++)
                    asm volatile("mma.sync.aligned.m16n8k16.row.col.f32.bf16.bf16.f32 "
                        "{%0,%1,%2,%3},{%4,%5,%6,%7},{%8,%9},{%0,%1,%2,%3};"
                        :"+f"(acc[f][n][0]),"+f"(acc[f][n][1]),"+f"(acc[f][n][2]),"+f"(acc[f][n][3])
                        :"r"(a[f][0]),"r"(a[f][1]),"r"(a[f][2]),"r"(a[f][3]),
                         "r"(bb[n][0]),"r"(bb[n][1]));
        }
        __syncthreads();
    }

    float* Cb=Cg+((size_t)(b*512+mb*128+wm*64))*LDC + nb*128 + wn*32;
    #pragma unroll
    for(int f=0;f<4;f++)
        #pragma unroll
        for(int n=0;n<4;n++){
            float2 v0=make_float2(acc[f][n][0],acc[f][n][1]);
            float2 v1=make_float2(acc[f][n][2],acc[f][n][3]);
            if(MODE==0){ v0.x=0.25f*(v0.x-64.f); v0.y=0.25f*(v0.y-64.f);
                         v1.x=0.25f*(v1.x-64.f); v1.y=0.25f*(v1.y-64.f); }
            *(float2*)(Cb+(size_t)(f*16+fr  )*LDC+n*8+fc*2)=v0;
            *(float2*)(Cb+(size_t)(f*16+fr+8)*LDC+n*8+fc*2)=v1;
        }
}

// ---------------------------------------------------------------- launch
extern "C" void kernel_launch(void* const* d_in, const int* in_sizes, int n_in,
                              void* d_out, int out_size)
{
    const float* q_mean=(const float*)d_in[0];
    const float* q_cov =(const float*)d_in[1];
    const float* k_mean=(const float*)d_in[2];
    const float* k_cov =(const float*)d_in[3];
    const float* v_mean=(const float*)d_in[4];
    const float* v_cov =(const float*)d_in[5];
    float* out=(float*)d_out;

    feat_kernel<<<2*BATCH*SQN,256>>>(q_mean,q_cov,k_mean,k_cov);
    vsplit_kernel<<<dim3(8,8,BATCH),256>>>(v_cov);
    // js: K = 3*1152 -> 108 chunks of 32
    gemm_mma<108,36,1152,2304,2304,512,512,0>
        <<<dim3(4,4,BATCH),256>>>(nullptr);
    softmax_kernel<<<BATCH*SQN,256>>>(v_mean,out);
    // out_cov: K = 3*512 -> 48 chunks of 32
    gemm_mma<48,16,512,1024,1024,1024,1024,1>
        <<<dim3(8,4,BATCH),256>>>(out+(size_t)BATCH*SQN*DDIM);
}

// round 7
// speedup vs baseline: 2.6110x; 2.0038x over previous
#include <cuda_runtime.h>
#include <cuda_bf16.h>
#include <cstdint>

#define BATCH 8
#define SQN 512
#define DDIM 32
typedef unsigned short u16;
typedef unsigned int u32;

// scratch (__device__ globals, referenced ONLY inside device code; zero-init)
static __device__ __align__(16) u16 g_F[(size_t)BATCH*SQN*2304];   // q feats [hi|lo]
static __device__ __align__(16) u16 g_G[(size_t)BATCH*SQN*2304];   // k feats [hi|lo]
static __device__ __align__(16) u16 g_S[(size_t)BATCH*SQN*1024];   // score  [hi|lo]
static __device__ __align__(16) u16 g_V[(size_t)BATCH*1152*1024];  // vcov^T + vmean^T [hi|lo]
static __device__ __align__(16) float g_js[(size_t)BATCH*SQN*SQN];

__device__ __forceinline__ u16 f2bf(float x){ __nv_bfloat16 h=__float2bfloat16(x); return *(u16*)&h; }
__device__ __forceinline__ float bf2f(u16 u){ __nv_bfloat16 h=*(__nv_bfloat16*)&u; return __bfloat162float(h); }
__device__ __forceinline__ u32 hilo(float x0,float x1,int lo){
    u16 h0=f2bf(x0), h1=f2bf(x1);
    if(lo){ h0=f2bf(x0-bf2f(h0)); h1=f2bf(x1-bf2f(h1)); }
    return (u32)h0 | ((u32)h1<<16);
}

// ---------------------------------------------------------------- featurize v2
// One warp per matrix. Lane c holds column c (== row c, symmetric) in registers.
// In-place Gauss-Jordan inversion (NR gaussj, no pivoting; SPD diag-dominant).
__global__ void __launch_bounds__(256) feat_kernel(
    const float* __restrict__ q_mean,const float* __restrict__ q_cov,
    const float* __restrict__ k_mean,const float* __restrict__ k_cov)
{
    __shared__ float inv_s[8][32*33];
    __shared__ float mean_sh[8][32];
    __shared__ float u_sh[8][32];
    __shared__ u16 dtab[528];

    const int tid=threadIdx.x, wid=tid>>5, lane=tid&31;
    // build packed-pair decode table once per block (same for all matrices)
    for(int t=tid;t<528;t+=256){
        int d=0,rem=t,len=32; while(rem>=len){rem-=len;++d;--len;}
        dtab[t]=(u16)((d<<8)|(d+rem));
    }

    const int gidx = blockIdx.x*8 + wid;          // 0..8191
    const bool is_k = gidx >= BATCH*SQN;
    const int idx = is_k ? gidx-BATCH*SQN : gidx;
    const float* cov =(is_k?k_cov :q_cov )+(size_t)idx*1024;
    const float* mean=(is_k?k_mean:q_mean)+(size_t)idx*32;

    float m[32];
    #pragma unroll
    for(int i=0;i<8;i++){
        float4 v=*(const float4*)(cov+lane*32+i*4);
        m[i*4]=v.x; m[i*4+1]=v.y; m[i*4+2]=v.z; m[i*4+3]=v.w;
    }
    float mean_v = mean[lane];
    __syncthreads();   // dtab ready

    // in-place GJ inversion: per pivot p:
    //   d=1/M[p][p]; row p: M[p][p]=1 then row*=d;
    //   for r!=p: f=M[r][p]; M[r][p]=0; row r -= f*row p
    #pragma unroll
    for(int p=0;p<32;p++){
        float colp[32];
        #pragma unroll
        for(int r=0;r<32;r++) colp[r]=__shfl_sync(0xffffffffu,m[r],p);
        float dpi = 1.f/colp[p];
        bool isp = (lane==p);
        float rowp = (isp?1.f:m[p])*dpi;
        m[p]=rowp;
        #pragma unroll
        for(int r=0;r<32;r++){
            if(r==p) continue;
            float base = isp ? 0.f : m[r];
            m[r] = fmaf(-colp[r], rowp, base);
        }
    }

    // u_c = sum_r Inv[r][c]*mean[r]  (Inv symmetric)
    float u=0.f;
    #pragma unroll
    for(int r=0;r<32;r++) u=fmaf(m[r],__shfl_sync(0xffffffffu,mean_v,r),u);
    float s = u*mean_v;
    #pragma unroll
    for(int o=16;o;o>>=1) s += __shfl_xor_sync(0xffffffffu,s,o);

    // stage inv rows + mean/u to smem for emission
    #pragma unroll
    for(int r=0;r<32;r++) inv_s[wid][r*33+lane]=m[r];
    mean_sh[wid][lane]=mean_v;
    u_sh[wid][lane]=u;
    __syncwarp();

    const float* iw = inv_s[wid];
    const float* ms = mean_sh[wid];
    const float* us = u_sh[wid];
    u32* rowp=(u32*)((is_k?g_G:g_F)+(size_t)idx*2304);

    #pragma unroll 1
    for(int i=0;i<18;i++){
        int j=i*32+lane;           // u32 index 0..575 (floats 2j,2j+1)
        float x0,x1;
        if(j<264){                  // section A: pairs t=2j,2j+1
            #pragma unroll
            for(int h=0;h<2;h++){
                int t=2*j+h;
                u16 de=dtab[t]; int d=de>>8, e=de&255;
                float cv=cov[d*32+e];
                float val=cv+ms[d]*ms[e];
                float iv=iw[d*33+e];
                float dbl=(d==e)?1.f:2.f;
                float x = is_k ? iv : val*dbl;
                if(h) x1=x; else x0=x;
            }
        } else if(j<528){           // section B: pairs t=2j-528, +1
            #pragma unroll
            for(int h=0;h<2;h++){
                int t=2*j-528+h;
                u16 de=dtab[t]; int d=de>>8, e=de&255;
                float cv=cov[d*32+e];
                float val=cv+ms[d]*ms[e];
                float iv=iw[d*33+e];
                float dbl=(d==e)?1.f:2.f;
                float x = is_k ? val : iv*dbl;
                if(h) x1=x; else x0=x;
            }
        } else if(j<544){           // floats 1056..1087
            int r=2*(j-528);
            if(!is_k){ x0=-2.f*ms[r]; x1=-2.f*ms[r+1]; }
            else     { x0=us[r];      x1=us[r+1];      }
        } else if(j<560){           // floats 1088..1119
            int r=2*(j-544);
            if(!is_k){ x0=-2.f*us[r]; x1=-2.f*us[r+1]; }
            else     { x0=ms[r];      x1=ms[r+1];      }
        } else if(j==560){          // floats 1120,1121
            if(!is_k){ x0=s; x1=1.f; } else { x0=1.f; x1=s; }
        } else { x0=0.f; x1=0.f; }  // pad
        rowp[j]    =hilo(x0,x1,0);
        rowp[576+j]=hilo(x0,x1,1);
    }
}

// ---------------------------------------------------------------- vcov transpose+split (rows 0..1023 of g_V per batch)
__global__ void __launch_bounds__(256) vsplit_kernel(const float* __restrict__ vcov)
{
    __shared__ float ts[64*129];
    const int n0=blockIdx.x*128, k0=blockIdx.y*64, b=blockIdx.z, tid=threadIdx.x;
    const float* src=vcov+((size_t)b*512+k0)*1024+n0;
    for(int i=tid;i<8192;i+=256){ int kk=i>>7,nn=i&127; ts[kk*129+nn]=src[(size_t)kk*1024+nn]; }
    __syncthreads();
    u32* dst=(u32*)g_V;
    for(int i=tid;i<4096;i+=256){
        int nl=i>>5, kp=i&31;
        float x0=ts[(kp*2)*129+nl], x1=ts[(kp*2+1)*129+nl];
        size_t rb=((size_t)b*1152+n0+nl)*512;
        dst[rb+(blockIdx.y*32)+kp]     =hilo(x0,x1,0);
        dst[rb+256+(blockIdx.y*32)+kp] =hilo(x0,x1,1);
    }
}

// ---------------------------------------------------------------- vmean transpose+split (rows 1024..1055 of g_V per batch)
__global__ void __launch_bounds__(256) vmsplit_kernel(const float* __restrict__ vmean)
{
    const int b=blockIdx.x, tid=threadIdx.x;
    for(int i=tid;i<32*512;i+=256){
        int d=i>>9, k=i&511;
        float x=vmean[((size_t)b*512+k)*32+d];
        u16 hi=f2bf(x), lo=f2bf(x-bf2f(hi));
        u16* row=g_V+((size_t)b*1152+1024+d)*1024;
        row[k]=hi; row[512+k]=lo;
    }
}

// ---------------------------------------------------------------- softmax -> score split only
__global__ void __launch_bounds__(256) softmax_kernel()
{
    __shared__ float p[512]; __shared__ float red[256];
    const int gid=blockIdx.x, tid=threadIdx.x;
    const float* row=g_js+(size_t)gid*512;
    float v0=row[tid], v1=row[tid+256];
    red[tid]=fmaxf(v0,v1); __syncthreads();
    for(int sft=128;sft>0;sft>>=1){ if(tid<sft) red[tid]=fmaxf(red[tid],red[tid+sft]); __syncthreads(); }
    float mx=red[0]; __syncthreads();
    float e0=__expf(v0-mx), e1=__expf(v1-mx);
    red[tid]=e0+e1; __syncthreads();
    for(int sft=128;sft>0;sft>>=1){ if(tid<sft) red[tid]+=red[tid+sft]; __syncthreads(); }
    float inv=1.f/red[0]; __syncthreads();
    p[tid]=e0*inv; p[tid+256]=e1*inv;
    __syncthreads();
    u32* srow=(u32*)(g_S+(size_t)gid*1024);
    float x0=p[2*tid], x1=p[2*tid+1];
    srow[tid]    =hilo(x0,x1,0);
    srow[256+tid]=hilo(x0,x1,1);
}

// ---------------------------------------------------------------- bf16 mma.sync GEMM
// MODE 0: js (A=g_F,B=g_G,C=g_js).  MODE 1: out_cov+out_mean (A=g_S,B=g_V).
// NT, 128x128 CTA tile, 8 warps (64x32 each), K-chunks of 32.
template<int NK,int KCH,int HL,int LDA,int LDB,int NBROWS,int LDC,int MODE>
__global__ void __launch_bounds__(256,2) gemm_mma(float* __restrict__ Carg,
                                                  float* __restrict__ Cmean)
{
    __shared__ __align__(16) u16 sA[128*40];   // 40 u16 = 80B row stride
    __shared__ __align__(16) u16 sB[128*40];
    const int tid=threadIdx.x, wid=tid>>5, lid=tid&31;
    const int wm=wid&1, wn=wid>>1;             // warp tile: rows wm*64, cols wn*32
    const int nb=blockIdx.x, mb=blockIdx.y, b=blockIdx.z;

    const u16* Ag = (MODE==0) ? g_F : g_S;     // device-side symbol resolution
    const u16* Bg = (MODE==0) ? g_G : g_V;
    float*     Cg = (MODE==0) ? g_js : Carg;

    const u16* Ab=Ag+(size_t)(b*512   +mb*128)*LDA;
    const u16* Bb=Bg+(size_t)(b*NBROWS+nb*128)*LDB;

    const int ar0=tid>>2, ac0=tid&3;
    const int ar1=(tid+256)>>2;
    uint4 ra0,ra1,rb0,rb1;

    auto gload=[&](int t){
        int blk=t/KCH, tt=t-blk*KCH;
        int aoff=((blk==2)?HL:0)+tt*32;
        int boff=((blk==1)?HL:0)+tt*32;
        ra0=*(const uint4*)(Ab+(size_t)ar0*LDA+aoff+ac0*8);
        ra1=*(const uint4*)(Ab+(size_t)ar1*LDA+aoff+ac0*8);
        rb0=*(const uint4*)(Bb+(size_t)ar0*LDB+boff+ac0*8);
        rb1=*(const uint4*)(Bb+(size_t)ar1*LDB+boff+ac0*8);
    };

    const int fr=lid>>2, fc=lid&3;   // PTX mma fragment lane decomposition
    float acc[4][4][4];
    #pragma unroll
    for(int f=0;f<4;f++)
        #pragma unroll
        for(int n=0;n<4;n++)
            #pragma unroll
            for(int e=0;e<4;e++) acc[f][n][e]=0.f;

    gload(0);
    #pragma unroll 1
    for(int t=0;t<NK;t++){
        *(uint4*)(sA+ar0*40+ac0*8)=ra0;
        *(uint4*)(sA+ar1*40+ac0*8)=ra1;
        *(uint4*)(sB+ar0*40+ac0*8)=rb0;
        *(uint4*)(sB+ar1*40+ac0*8)=rb1;
        __syncthreads();
        if(t+1<NK) gload(t+1);
        #pragma unroll
        for(int ks=0;ks<2;ks++){
            u32 a[4][4], bb[4][2];
            #pragma unroll
            for(int f=0;f<4;f++){
                const u16* base=sA+(wm*64+f*16+fr)*40+ks*16+fc*2;
                a[f][0]=*(const u32*)(base);
                a[f][1]=*(const u32*)(base+8*40);
                a[f][2]=*(const u32*)(base+8);
                a[f][3]=*(const u32*)(base+8*40+8);
            }
            #pragma unroll
            for(int n=0;n<4;n++){
                const u16* base=sB+(wn*32+n*8+fr)*40+ks*16+fc*2;
                bb[n][0]=*(const u32*)(base);
                bb[n][1]=*(const u32*)(base+8);
            }
            #pragma unroll
            for(int f=0;f<4;f++)
                #pragma unroll
                for(int n=0;n<4;n++)
                    asm volatile("mma.sync.aligned.m16n8k16.row.col.f32.bf16.bf16.f32 "
                        "{%0,%1,%2,%3},{%4,%5,%6,%7},{%8,%9},{%0,%1,%2,%3};"
                        :"+f"(acc[f][n][0]),"+f"(acc[f][n][1]),"+f"(acc[f][n][2]),"+f"(acc[f][n][3])
                        :"r"(a[f][0]),"r"(a[f][1]),"r"(a[f][2]),"r"(a[f][3]),
                         "r"(bb[n][0]),"r"(bb[n][1]));
        }
        __syncthreads();
    }

    if(MODE==1 && nb==8){
        // out_mean tile: B rows 1024..1055 are vmean^T; only wn==0 (cols 0..31) valid
        if(wn!=0) return;
        float* Cb=Cmean+((size_t)(b*512+mb*128+wm*64))*32;
        #pragma unroll
        for(int f=0;f<4;f++)
            #pragma unroll
            for(int n=0;n<4;n++){
                *(float2*)(Cb+(size_t)(f*16+fr  )*32+n*8+fc*2)=make_float2(acc[f][n][0],acc[f][n][1]);
                *(float2*)(Cb+(size_t)(f*16+fr+8)*32+n*8+fc*2)=make_float2(acc[f][n][2],acc[f][n][3]);
            }
        return;
    }

    float* Cb=Cg+((size_t)(b*512+mb*128+wm*64))*LDC + nb*128 + wn*32;
    #pragma unroll
    for(int f=0;f<4;f++)
        #pragma unroll
        for(int n=0;n<4;n++){
            float2 v0=make_float2(acc[f][n][0],acc[f][n][1]);
            float2 v1=make_float2(acc[f][n][2],acc[f][n][3]);
            if(MODE==0){ v0.x=0.25f*(v0.x-64.f); v0.y=0.25f*(v0.y-64.f);
                         v1.x=0.25f*(v1.x-64.f); v1.y=0.25f*(v1.y-64.f); }
            *(float2*)(Cb+(size_t)(f*16+fr  )*LDC+n*8+fc*2)=v0;
            *(float2*)(Cb+(size_t)(f*16+fr+8)*LDC+n*8+fc*2)=v1;
        }
}

// ---------------------------------------------------------------- launch
extern "C" void kernel_launch(void* const* d_in, const int* in_sizes, int n_in,
                              void* d_out, int out_size)
{
    const float* q_mean=(const float*)d_in[0];
    const float* q_cov =(const float*)d_in[1];
    const float* k_mean=(const float*)d_in[2];
    const float* k_cov =(const float*)d_in[3];
    const float* v_mean=(const float*)d_in[4];
    const float* v_cov =(const float*)d_in[5];
    float* out=(float*)d_out;

    feat_kernel<<<2*BATCH*SQN/8,256>>>(q_mean,q_cov,k_mean,k_cov);
    vsplit_kernel<<<dim3(8,8,BATCH),256>>>(v_cov);
    vmsplit_kernel<<<BATCH,256>>>(v_mean);
    // js: K = 3*1152 -> 108 chunks of 32
    gemm_mma<108,36,1152,2304,2304,512,512,0>
        <<<dim3(4,4,BATCH),256>>>(nullptr,nullptr);
    softmax_kernel<<<BATCH*SQN,256>>>();
    // out_cov (+fused out_mean as 9th N-tile): K = 3*512 -> 48 chunks of 32
    gemm_mma<48,16,512,1024,1024,1152,1024,1>
        <<<dim3(9,4,BATCH),256>>>(out+(size_t)BATCH*SQN*DDIM, out);
}